// round 14
// baseline (speedup 1.0000x reference)
#include <cuda_runtime.h>
#include <cuda_bf16.h>
#include <math.h>

#define B_   2
#define S_   2048
#define H_   2048
#define NH_  16
#define D_   128
#define LAT_ 512
#define MS_  (B_*S_)   // 4096 rows total

// ---------------- scratch (device globals; no allocation allowed) ----------
// fused rows: [c_kv(512) | k_r(128)] stride 640 (same for q)
__device__ float g_ckv[MS_*640];
__device__ float g_cq [MS_*640];
__device__ float g_ctx[MS_*H_];
__device__ float g_bKV[640];
__device__ float g_bQ [640];

// pre-split bf16 activations for attention
__device__ __nv_bfloat16 g_khi [MS_*H_], g_klo [MS_*H_];   // K_c  [row][H]
__device__ __nv_bfloat16 g_qhi [MS_*H_], g_qlo [MS_*H_];   // Q_c  [row][H]
__device__ __nv_bfloat16 g_vthi[MS_*H_], g_vtlo[MS_*H_];   // V^T  [H][MS]
__device__ __nv_bfloat16 g_krh [MS_*D_], g_krl [MS_*D_];   // rope(K_r)
__device__ __nv_bfloat16 g_qrh [MS_*D_], g_qrl [MS_*D_];   // rope(Q_r)

// pre-split / transposed bf16 weights ([N][K] layout), hi + lo residual
#define OFF_DKV 0                    // 640 x 2048 (DKV rows 0-511, KR rows 512-639)
#define OFF_KR  1048576
#define OFF_DQ  1310720              // 640 x 2048
#define OFF_QR  2359296
#define OFF_UK  2621440              // 2048 x 512
#define OFF_UV  3670016
#define OFF_UQ  4718592
#define OFF_O   5767168              // 2048 x 2048
#define WTOT    9961472
__device__ __nv_bfloat16 g_whi[WTOT];
__device__ __nv_bfloat16 g_wlo[WTOT];

// ---------------- weight split + transpose: W[K][N] -> hi/lo [N][K] --------
__global__ void split_transpose(const float* __restrict__ W,
                                __nv_bfloat16* __restrict__ hi,
                                __nv_bfloat16* __restrict__ lo,
                                int K, int N)
{
    __shared__ float tile[32][33];
    const int k0 = blockIdx.y * 32, n0 = blockIdx.x * 32;
    const int tx = threadIdx.x, ty = threadIdx.y;   // 32 x 8
#pragma unroll
    for (int i = ty; i < 32; i += 8)
        tile[i][tx] = W[(k0 + i) * N + n0 + tx];
    __syncthreads();
#pragma unroll
    for (int i = ty; i < 32; i += 8) {
        float v = tile[tx][i];
        __nv_bfloat16 h = __float2bfloat16(v);
        float r = v - __bfloat162float(h);
        hi[(n0 + i) * (long)K + k0 + tx] = h;
        lo[(n0 + i) * (long)K + k0 + tx] = __float2bfloat16(r);
    }
}

// ---------------- split helper: float4 -> packed bf16 hi/lo ----------------
__device__ __forceinline__ void split4(float4 v, uint2& h, uint2& l)
{
    __nv_bfloat162 h0 = __floats2bfloat162_rn(v.x, v.y);
    __nv_bfloat162 h1 = __floats2bfloat162_rn(v.z, v.w);
    float2 f0 = __bfloat1622float2(h0);
    float2 f1 = __bfloat1622float2(h1);
    __nv_bfloat162 l0 = __floats2bfloat162_rn(v.x - f0.x, v.y - f0.y);
    __nv_bfloat162 l1 = __floats2bfloat162_rn(v.z - f1.x, v.w - f1.y);
    h.x = *(unsigned*)&h0; h.y = *(unsigned*)&h1;
    l.x = *(unsigned*)&l0; l.y = *(unsigned*)&l1;
}

__device__ __forceinline__ void mma16816(float* c, const unsigned* a,
                                         unsigned b0, unsigned b1)
{
    asm volatile(
        "mma.sync.aligned.m16n8k16.row.col.f32.bf16.bf16.f32 "
        "{%0,%1,%2,%3}, {%4,%5,%6,%7}, {%8,%9}, {%0,%1,%2,%3};\n"
        : "+f"(c[0]), "+f"(c[1]), "+f"(c[2]), "+f"(c[3])
        : "r"(a[0]), "r"(a[1]), "r"(a[2]), "r"(a[3]), "r"(b0), "r"(b1));
}

// ---------------- bf16-split tensor-core GEMM ------------------------------
// C[M][N] = A[M][K](fp32, row stride lda) @ W(pre-split bf16 [N][K]) + bias.
// 3-pass hi/lo, BM=128, BN=128, BK=32, 256 threads, single-stage smem with
// register prefetch. __launch_bounds__(256,2) caps regs at 128 -> 2 CTAs/SM.
// MODE 0: fp32 C. MODE 1: bf16 hi/lo row-major. MODE 2: bf16 hi/lo transposed.
template<int MODE>
__global__ __launch_bounds__(256, 2) void gemm_bf16s(
    const float* __restrict__ A,
    const __nv_bfloat16* __restrict__ Bhi, const __nv_bfloat16* __restrict__ Blo,
    const float* __restrict__ bias, float* __restrict__ C,
    __nv_bfloat16* __restrict__ Chi, __nv_bfloat16* __restrict__ Clo,
    int M, int N, int K, int lda)
{
    __shared__ __align__(16) __nv_bfloat16 sm[4][128][40];
    // sm[0]=Ah  sm[1]=Al  sm[2]=Bh  sm[3]=Bl

    const int tid  = threadIdx.x;
    const int wid  = tid >> 5, lane = tid & 31;
    const int row0 = blockIdx.y * 128, col0 = blockIdx.x * 128;
    const int wm   = (wid >> 1) * 32, wn = (wid & 1) * 64;

    float acc[2][8][4];
#pragma unroll
    for (int t = 0; t < 2; t++)
#pragma unroll
        for (int n = 0; n < 8; n++)
#pragma unroll
            for (int j = 0; j < 4; j++) acc[t][n][j] = 0.f;

    float4 av[4], bhv[2], blv[2];

    // coalesced load mappings: A warp reads 4 consecutive rows (128B each);
    // B warp reads 8 consecutive rows (64B each).
#define LOAD_AB(k0)                                                        \
    {                                                                      \
        _Pragma("unroll")                                                  \
        for (int it = 0; it < 4; it++) {                                   \
            int slot = it * 256 + tid;                                     \
            int ar = slot >> 3, ac = (slot & 7) * 4;                       \
            av[it] = *(const float4*)&A[(long)(row0 + ar) * lda + (k0) + ac]; \
        }                                                                  \
        _Pragma("unroll")                                                  \
        for (int it = 0; it < 2; it++) {                                   \
            int slot = it * 256 + tid;                                     \
            int bn = slot >> 2, bc = (slot & 3) * 8;                       \
            bhv[it] = *(const float4*)&Bhi[(long)(col0 + bn) * K + (k0) + bc]; \
            blv[it] = *(const float4*)&Blo[(long)(col0 + bn) * K + (k0) + bc]; \
        }                                                                  \
    }

    LOAD_AB(0);

    for (int k0 = 0; k0 < K; k0 += 32) {
        __syncthreads();
        // store prefetched tile to smem (split A on the fly)
#pragma unroll
        for (int it = 0; it < 4; it++) {
            int slot = it * 256 + tid;
            int ar = slot >> 3, ac = (slot & 7) * 4;
            uint2 hh, ll;
            split4(av[it], hh, ll);
            *(uint2*)&sm[0][ar][ac] = hh;
            *(uint2*)&sm[1][ar][ac] = ll;
        }
#pragma unroll
        for (int it = 0; it < 2; it++) {
            int slot = it * 256 + tid;
            int bn = slot >> 2, bc = (slot & 3) * 8;
            *(float4*)&sm[2][bn][bc] = bhv[it];
            *(float4*)&sm[3][bn][bc] = blv[it];
        }
        __syncthreads();

        if (k0 + 32 < K) LOAD_AB(k0 + 32);

#pragma unroll
        for (int s = 0; s < 2; s++) {
            const int c = s * 16 + (lane & 3) * 2;
            unsigned afh[2][4], afl[2][4];
#pragma unroll
            for (int t = 0; t < 2; t++) {
                int r = wm + t * 16 + (lane >> 2);
                afh[t][0] = *(unsigned*)&sm[0][r][c];
                afh[t][1] = *(unsigned*)&sm[0][r + 8][c];
                afh[t][2] = *(unsigned*)&sm[0][r][c + 8];
                afh[t][3] = *(unsigned*)&sm[0][r + 8][c + 8];
                afl[t][0] = *(unsigned*)&sm[1][r][c];
                afl[t][1] = *(unsigned*)&sm[1][r + 8][c];
                afl[t][2] = *(unsigned*)&sm[1][r][c + 8];
                afl[t][3] = *(unsigned*)&sm[1][r + 8][c + 8];
            }
#pragma unroll
            for (int nt = 0; nt < 8; nt++) {
                int n = wn + nt * 8 + (lane >> 2);
                unsigned bh0 = *(unsigned*)&sm[2][n][c];
                unsigned bh1 = *(unsigned*)&sm[2][n][c + 8];
                unsigned bl0 = *(unsigned*)&sm[3][n][c];
                unsigned bl1 = *(unsigned*)&sm[3][n][c + 8];
#pragma unroll
                for (int t = 0; t < 2; t++) {
                    mma16816(acc[t][nt], afh[t], bh0, bh1);
                    mma16816(acc[t][nt], afh[t], bl0, bl1);
                    mma16816(acc[t][nt], afl[t], bh0, bh1);
                }
            }
        }
    }

#pragma unroll
    for (int t = 0; t < 2; t++) {
        int gr = row0 + wm + t * 16 + (lane >> 2);
#pragma unroll
        for (int nt = 0; nt < 8; nt++) {
            int gc = col0 + wn + nt * 8 + (lane & 3) * 2;
            float2 bv = *(const float2*)&bias[gc];
            float v0 = acc[t][nt][0] + bv.x, v1 = acc[t][nt][1] + bv.y;
            float v2 = acc[t][nt][2] + bv.x, v3 = acc[t][nt][3] + bv.y;
            if (MODE == 0) {
                *(float2*)&C[(long)gr * N + gc]       = make_float2(v0, v1);
                *(float2*)&C[(long)(gr + 8) * N + gc] = make_float2(v2, v3);
            } else if (MODE == 1) {
                __nv_bfloat162 h01 = __floats2bfloat162_rn(v0, v1);
                float2 f01 = __bfloat1622float2(h01);
                __nv_bfloat162 q01 = __floats2bfloat162_rn(v0 - f01.x, v1 - f01.y);
                __nv_bfloat162 h23 = __floats2bfloat162_rn(v2, v3);
                float2 f23 = __bfloat1622float2(h23);
                __nv_bfloat162 q23 = __floats2bfloat162_rn(v2 - f23.x, v3 - f23.y);
                *(__nv_bfloat162*)&Chi[(long)gr * N + gc]       = h01;
                *(__nv_bfloat162*)&Clo[(long)gr * N + gc]       = q01;
                *(__nv_bfloat162*)&Chi[(long)(gr + 8) * N + gc] = h23;
                *(__nv_bfloat162*)&Clo[(long)(gr + 8) * N + gc] = q23;
            } else {
                float vs[4] = {v0, v1, v2, v3};
#pragma unroll
                for (int q = 0; q < 4; q++) {
                    long idx = (long)(gc + (q & 1)) * MS_ + gr + (q >> 1) * 8;
                    __nv_bfloat16 hh = __float2bfloat16(vs[q]);
                    Chi[idx] = hh;
                    Clo[idx] = __float2bfloat16(vs[q] - __bfloat162float(hh));
                }
            }
        }
    }
#undef LOAD_AB
}

// ---------------- rope: fp32 in (strided) -> bf16 hi/lo out ----------------
__global__ void rope_kernel(const float* __restrict__ x, int ldx,
                            __nv_bfloat16* __restrict__ oh,
                            __nv_bfloat16* __restrict__ ol)
{
    int row = blockIdx.x;
    int d   = threadIdx.x;
    __shared__ float buf[128];
    buf[d] = x[(long)row * ldx + d];
    __syncthreads();
    int i = d & 63;
    float inv = (float)exp(-(double)(2 * i) / 128.0 * 9.210340371976184);
    float ang = (float)(row & (S_ - 1)) * inv;
    float s, c;
    sincosf(ang, &s, &c);
    float y = (d < 64) ? (buf[d] * c - buf[d + 64] * s)
                       : (buf[d - 64] * s + buf[d] * c);
    __nv_bfloat16 h = __float2bfloat16(y);
    oh[row * D_ + d] = h;
    ol[row * D_ + d] = __float2bfloat16(y - __bfloat162float(h));
}

// ---------------- coalesced Q/K tile loader --------------------------------
// Loads 64 rows x 256 dims (hi+lo) into DH/DL (stride 264 bf16). Each
// half-warp reads one 256B contiguous row segment per iteration.
__device__ __forceinline__ void load_qk_tile(
    __nv_bfloat16* DH, __nv_bfloat16* DL,
    const __nv_bfloat16* __restrict__ chi_, const __nv_bfloat16* __restrict__ clo_,
    const __nv_bfloat16* __restrict__ rh_,  const __nv_bfloat16* __restrict__ rl_,
    long rowbase, int hD, int t)
{
#pragma unroll
    for (int it = 0; it < 16; it++) {
        int seg = (t >> 4) + it * 16;       // 0..255
        int row = seg >> 2, src = seg & 3;  // 0=c-hi 1=r-hi 2=c-lo 3=r-lo
        int c16 = t & 15;
        long rg = rowbase + row;
        const uint4* s;
        if (src == 0)      s = (const uint4*)(chi_ + rg * H_ + hD) + c16;
        else if (src == 1) s = (const uint4*)(rh_  + rg * D_)      + c16;
        else if (src == 2) s = (const uint4*)(clo_ + rg * H_ + hD) + c16;
        else               s = (const uint4*)(rl_  + rg * D_)      + c16;
        __nv_bfloat16* db = (src & 2) ? DL : DH;
        *((uint4*)(db + row * 264 + (src & 1) * 128) + c16) = *s;
    }
}

// ---------------- tensor-core flash attention (bf16 3-pass split) ----------
#define AT_SMEM 191744
__global__ __launch_bounds__(256, 1) void mla_attn_mma(
    const __nv_bfloat16* __restrict__ qhi, const __nv_bfloat16* __restrict__ qlo,
    const __nv_bfloat16* __restrict__ qrh, const __nv_bfloat16* __restrict__ qrl,
    const __nv_bfloat16* __restrict__ khi, const __nv_bfloat16* __restrict__ klo,
    const __nv_bfloat16* __restrict__ krh, const __nv_bfloat16* __restrict__ krl,
    const __nv_bfloat16* __restrict__ vth, const __nv_bfloat16* __restrict__ vtl,
    const int* __restrict__ mask, float* __restrict__ ctx)
{
    extern __shared__ __align__(16) char smx[];
    __nv_bfloat16* QH = (__nv_bfloat16*)smx;
    __nv_bfloat16* QL = QH + 64 * 264;
    __nv_bfloat16* KH = QL + 64 * 264;
    __nv_bfloat16* KL = KH + 64 * 264;
    __nv_bfloat16* VH = KL + 64 * 264;
    __nv_bfloat16* VL = VH + 128 * 72;
    __nv_bfloat16* PH = VL + 128 * 72;
    __nv_bfloat16* PL = PH + 64 * 72;
    float*         MB = (float*)(PL + 64 * 72);
    float*         SMX = MB + 64;
    float*         SMS = SMX + 128;

    const int t    = threadIdx.x;
    const int lane = t & 31, w = t >> 5;
    const int wg   = w >> 2, wr = w & 3;
    const int b = blockIdx.z, h = blockIdx.y;
    const int q0 = blockIdx.x * 64;
    const int r0 = wr * 16;
    const int ru = lane >> 2, rv = lane & 3;

    load_qk_tile(QH, QL, qhi, qlo, qrh, qrl, (long)(b * S_ + q0), h * D_, t);

    float oacc[16][4];
#pragma unroll
    for (int i = 0; i < 16; i++)
#pragma unroll
        for (int j = 0; j < 4; j++) oacc[i][j] = 0.f;
    float m0 = -1e30f, m1 = -1e30f, l0 = 0.f, l1 = 0.f;
    const float scale = 0.08838834764831845f;   // 1/sqrt(128)

    const unsigned* QHw = (const unsigned*)QH;
    const unsigned* QLw = (const unsigned*)QL;
    const unsigned* KHw = (const unsigned*)KH;
    const unsigned* KLw = (const unsigned*)KL;
    const unsigned* VHw = (const unsigned*)VH;
    const unsigned* VLw = (const unsigned*)VL;
    unsigned* PHw = (unsigned*)PH;
    unsigned* PLw = (unsigned*)PL;

    for (int s0 = 0; s0 < S_; s0 += 64) {
        __syncthreads();
        load_qk_tile(KH, KL, khi, klo, krh, krl, (long)(b * S_ + s0), h * D_, t);
        // V^T tile: each quarter-warp reads one 128B contiguous row segment
#pragma unroll
        for (int it = 0; it < 8; it++) {
            int slot = t + it * 256;
            int seg = slot >> 3, c4 = slot & 7;
            int vd = seg & 127, hl = seg >> 7;
            const __nv_bfloat16* sb = hl ? vtl : vth;
            const uint4* s = (const uint4*)(sb + (long)(h * D_ + vd) * MS_ + b * S_ + s0) + c4;
            __nv_bfloat16* db = hl ? VL : VH;
            *((uint4*)(db + vd * 72) + c4) = *s;
        }
        if (t < 64) MB[t] = mask[b * S_ + s0 + t] ? 0.f : -1e30f;
        __syncthreads();

        // ---- QK^T (3-pass), this group's 4 column tiles ----
        float sacc[4][4];
#pragma unroll
        for (int i = 0; i < 4; i++)
#pragma unroll
            for (int j = 0; j < 4; j++) sacc[i][j] = 0.f;
#pragma unroll 1
        for (int ch = 0; ch < 16; ch++) {
            unsigned ah[4], al[4];
            int ab = (r0 + ru) * 132 + ch * 8 + rv;
            ah[0] = QHw[ab];     ah[1] = QHw[ab + 8*132];
            ah[2] = QHw[ab + 4]; ah[3] = QHw[ab + 8*132 + 4];
            al[0] = QLw[ab];     al[1] = QLw[ab + 8*132];
            al[2] = QLw[ab + 4]; al[3] = QLw[ab + 8*132 + 4];
#pragma unroll
            for (int nt = 0; nt < 4; nt++) {
                int gnt = wg * 4 + nt;
                int bb = (gnt * 8 + ru) * 132 + ch * 8 + rv;
                unsigned bh0 = KHw[bb], bh1 = KHw[bb + 4];
                unsigned bl0 = KLw[bb], bl1 = KLw[bb + 4];
                mma16816(sacc[nt], ah, bh0, bh1);
                mma16816(sacc[nt], ah, bl0, bl1);
                mma16816(sacc[nt], al, bh0, bh1);
            }
        }

        // ---- partial row max ----
        float mx0 = -1e30f, mx1 = -1e30f;
#pragma unroll
        for (int nt = 0; nt < 4; nt++) {
            int col = (wg * 4 + nt) * 8 + rv * 2;
            float mb0 = MB[col], mb1 = MB[col + 1];
            sacc[nt][0] = sacc[nt][0] * scale + mb0;
            sacc[nt][1] = sacc[nt][1] * scale + mb1;
            sacc[nt][2] = sacc[nt][2] * scale + mb0;
            sacc[nt][3] = sacc[nt][3] * scale + mb1;
            mx0 = fmaxf(mx0, fmaxf(sacc[nt][0], sacc[nt][1]));
            mx1 = fmaxf(mx1, fmaxf(sacc[nt][2], sacc[nt][3]));
        }
        mx0 = fmaxf(mx0, __shfl_xor_sync(0xffffffffu, mx0, 1));
        mx0 = fmaxf(mx0, __shfl_xor_sync(0xffffffffu, mx0, 2));
        mx1 = fmaxf(mx1, __shfl_xor_sync(0xffffffffu, mx1, 1));
        mx1 = fmaxf(mx1, __shfl_xor_sync(0xffffffffu, mx1, 2));
        if (rv == 0) {
            SMX[wg * 64 + r0 + ru]     = mx0;
            SMX[wg * 64 + r0 + ru + 8] = mx1;
        }
        __syncthreads();
        float gm0 = fmaxf(SMX[r0 + ru],     SMX[64 + r0 + ru]);
        float gm1 = fmaxf(SMX[r0 + ru + 8], SMX[64 + r0 + ru + 8]);
        float mn0 = fmaxf(m0, gm0), mn1 = fmaxf(m1, gm1);
        float cr0 = __expf(m0 - mn0), cr1 = __expf(m1 - mn1);
        m0 = mn0; m1 = mn1;
#pragma unroll
        for (int nt = 0; nt < 16; nt++) {
            oacc[nt][0] *= cr0; oacc[nt][1] *= cr0;
            oacc[nt][2] *= cr1; oacc[nt][3] *= cr1;
        }
        float rs0 = 0.f, rs1 = 0.f;
#pragma unroll
        for (int nt = 0; nt < 4; nt++) {
            float p0 = __expf(sacc[nt][0] - mn0), p1 = __expf(sacc[nt][1] - mn0);
            float p2 = __expf(sacc[nt][2] - mn1), p3 = __expf(sacc[nt][3] - mn1);
            rs0 += p0 + p1; rs1 += p2 + p3;
            __nv_bfloat162 h01 = __floats2bfloat162_rn(p0, p1);
            float2 f01 = __bfloat1622float2(h01);
            __nv_bfloat162 q01 = __floats2bfloat162_rn(p0 - f01.x, p1 - f01.y);
            __nv_bfloat162 h23 = __floats2bfloat162_rn(p2, p3);
            float2 f23 = __bfloat1622float2(h23);
            __nv_bfloat162 q23 = __floats2bfloat162_rn(p2 - f23.x, p3 - f23.y);
            int gnt = wg * 4 + nt;
            int w0 = (r0 + ru) * 36 + gnt * 4 + rv;
            int w1 = (r0 + ru + 8) * 36 + gnt * 4 + rv;
            PHw[w0] = *(unsigned*)&h01; PLw[w0] = *(unsigned*)&q01;
            PHw[w1] = *(unsigned*)&h23; PLw[w1] = *(unsigned*)&q23;
        }
        rs0 += __shfl_xor_sync(0xffffffffu, rs0, 1);
        rs0 += __shfl_xor_sync(0xffffffffu, rs0, 2);
        rs1 += __shfl_xor_sync(0xffffffffu, rs1, 1);
        rs1 += __shfl_xor_sync(0xffffffffu, rs1, 2);
        if (rv == 0) {
            SMS[wg * 64 + r0 + ru]     = rs0;
            SMS[wg * 64 + r0 + ru + 8] = rs1;
        }
        __syncthreads();
        l0 = l0 * cr0 + SMS[r0 + ru]     + SMS[64 + r0 + ru];
        l1 = l1 * cr1 + SMS[r0 + ru + 8] + SMS[64 + r0 + ru + 8];

        // ---- P @ V (3-pass), this group's 32 keys ----
#pragma unroll 1
        for (int chl = 0; chl < 2; chl++) {
            int ch = wg * 2 + chl;
            unsigned ph[4], pl[4];
            int ab = (r0 + ru) * 36 + ch * 8 + rv;
            ph[0] = PHw[ab];     ph[1] = PHw[ab + 8*36];
            ph[2] = PHw[ab + 4]; ph[3] = PHw[ab + 8*36 + 4];
            pl[0] = PLw[ab];     pl[1] = PLw[ab + 8*36];
            pl[2] = PLw[ab + 4]; pl[3] = PLw[ab + 8*36 + 4];
#pragma unroll
            for (int nt = 0; nt < 16; nt++) {
                int bb = (nt * 8 + ru) * 36 + ch * 8 + rv;
                unsigned vh0 = VHw[bb], vh1 = VHw[bb + 4];
                unsigned vl0 = VLw[bb], vl1 = VLw[bb + 4];
                mma16816(oacc[nt], ph, vh0, vh1);
                mma16816(oacc[nt], ph, vl0, vl1);
                mma16816(oacc[nt], pl, vh0, vh1);
            }
        }
    }

    // ---- combine the two groups' partial PV sums ----
    __syncthreads();
    float* OC = (float*)KH;
    if (wg == 1) {
#pragma unroll
        for (int nt = 0; nt < 16; nt++) {
            int d0 = nt * 8 + rv * 2;
            *(float2*)&OC[(r0 + ru) * 132 + d0] =
                make_float2(oacc[nt][0], oacc[nt][1]);
            *(float2*)&OC[(r0 + ru + 8) * 132 + d0] =
                make_float2(oacc[nt][2], oacc[nt][3]);
        }
    }
    __syncthreads();
    if (wg == 0) {
        float inv0 = 1.f / l0, inv1 = 1.f / l1;
        long row0 = (long)(b * S_ + q0 + r0 + ru);
#pragma unroll
        for (int nt = 0; nt < 16; nt++) {
            int d0 = nt * 8 + rv * 2;
            float2 pB0 = *(float2*)&OC[(r0 + ru) * 132 + d0];
            float2 pB1 = *(float2*)&OC[(r0 + ru + 8) * 132 + d0];
            *(float2*)&ctx[row0 * H_ + h * D_ + d0] =
                make_float2((oacc[nt][0] + pB0.x) * inv0,
                            (oacc[nt][1] + pB0.y) * inv0);
            *(float2*)&ctx[(row0 + 8) * H_ + h * D_ + d0] =
                make_float2((oacc[nt][2] + pB1.x) * inv1,
                            (oacc[nt][3] + pB1.y) * inv1);
        }
    }
}

// ---------------- launch ----------------------------------------------------
extern "C" void kernel_launch(void* const* d_in, const int* in_sizes, int n_in,
                              void* d_out, int out_size)
{
    const float* hs    = (const float*)d_in[0];
    const int*   mask  = (const int*)  d_in[1];
    const float* W_DKV = (const float*)d_in[2];  const float* b_DKV = (const float*)d_in[3];
    const float* W_DQ  = (const float*)d_in[4];  const float* b_DQ  = (const float*)d_in[5];
    const float* W_UK  = (const float*)d_in[6];  const float* b_UK  = (const float*)d_in[7];
    const float* W_UV  = (const float*)d_in[8];  const float* b_UV  = (const float*)d_in[9];
    const float* W_UQ  = (const float*)d_in[10]; const float* b_UQ  = (const float*)d_in[11];
    const float* W_KR  = (const float*)d_in[12]; const float* b_KR  = (const float*)d_in[13];
    const float* W_QR  = (const float*)d_in[14]; const float* b_QR  = (const float*)d_in[15];
    const float* W_O   = (const float*)d_in[16]; const float* b_O   = (const float*)d_in[17];
    float* out = (float*)d_out;

    float *ckv, *cq, *ctx, *bkv, *bq;
    __nv_bfloat16 *whi, *wlo;
    __nv_bfloat16 *khi, *klo, *qhi, *qlo, *vthi, *vtlo, *krh, *krl, *qrh, *qrl;
    cudaGetSymbolAddress((void**)&ckv,  g_ckv);
    cudaGetSymbolAddress((void**)&cq,   g_cq);
    cudaGetSymbolAddress((void**)&ctx,  g_ctx);
    cudaGetSymbolAddress((void**)&bkv,  g_bKV);
    cudaGetSymbolAddress((void**)&bq,   g_bQ);
    cudaGetSymbolAddress((void**)&whi,  g_whi);
    cudaGetSymbolAddress((void**)&wlo,  g_wlo);
    cudaGetSymbolAddress((void**)&khi,  g_khi);
    cudaGetSymbolAddress((void**)&klo,  g_klo);
    cudaGetSymbolAddress((void**)&qhi,  g_qhi);
    cudaGetSymbolAddress((void**)&qlo,  g_qlo);
    cudaGetSymbolAddress((void**)&vthi, g_vthi);
    cudaGetSymbolAddress((void**)&vtlo, g_vtlo);
    cudaGetSymbolAddress((void**)&krh,  g_krh);
    cudaGetSymbolAddress((void**)&krl,  g_krl);
    cudaGetSymbolAddress((void**)&qrh,  g_qrh);
    cudaGetSymbolAddress((void**)&qrl,  g_qrl);

    cudaFuncSetAttribute(mla_attn_mma,
                         cudaFuncAttributeMaxDynamicSharedMemorySize, AT_SMEM);

    const dim3 blk(256);
    const dim3 tblk(32, 8);

    // fused biases
    cudaMemcpyAsync(bkv,       b_DKV, 512 * 4, cudaMemcpyDeviceToDevice);
    cudaMemcpyAsync(bkv + 512, b_KR,  128 * 4, cudaMemcpyDeviceToDevice);
    cudaMemcpyAsync(bq,        b_DQ,  512 * 4, cudaMemcpyDeviceToDevice);
    cudaMemcpyAsync(bq + 512,  b_QR,  128 * 4, cudaMemcpyDeviceToDevice);

    // weight splits first 5, so launch #6 (ncu -s 5 -c 1) is the fused DKV GEMM
    split_transpose<<<dim3(LAT_/32, H_/32), tblk>>>(W_DKV, whi+OFF_DKV, wlo+OFF_DKV, H_, LAT_); // 1
    split_transpose<<<dim3(D_/32,   H_/32), tblk>>>(W_KR,  whi+OFF_KR,  wlo+OFF_KR,  H_, D_);   // 2
    split_transpose<<<dim3(LAT_/32, H_/32), tblk>>>(W_DQ,  whi+OFF_DQ,  wlo+OFF_DQ,  H_, LAT_); // 3
    split_transpose<<<dim3(D_/32,   H_/32), tblk>>>(W_QR,  whi+OFF_QR,  wlo+OFF_QR,  H_, D_);   // 4
    split_transpose<<<dim3(H_/32,  LAT_/32), tblk>>>(W_UK, whi+OFF_UK,  wlo+OFF_UK,  LAT_, H_); // 5

    // fused down-projections: rows = [c_kv | k_r] (stride 640)
    gemm_bf16s<0><<<dim3(5, MS_/128), blk>>>(hs, whi+OFF_DKV, wlo+OFF_DKV, bkv,
                                             ckv, nullptr, nullptr, MS_, 640, H_, H_);          // 6 (profiled)
    split_transpose<<<dim3(H_/32,  LAT_/32), tblk>>>(W_UV, whi+OFF_UV,  wlo+OFF_UV,  LAT_, H_); // 7
    split_transpose<<<dim3(H_/32,  LAT_/32), tblk>>>(W_UQ, whi+OFF_UQ,  wlo+OFF_UQ,  LAT_, H_); // 8
    gemm_bf16s<0><<<dim3(5, MS_/128), blk>>>(hs, whi+OFF_DQ, wlo+OFF_DQ, bq,
                                             cq, nullptr, nullptr, MS_, 640, H_, H_);           // 9
    rope_kernel<<<MS_, 128>>>(ckv + 512, 640, krh, krl);                                        // 10
    rope_kernel<<<MS_, 128>>>(cq + 512, 640, qrh, qrl);                                         // 11

    // up-projections (A = c_kv / c_q with row stride 640)
    gemm_bf16s<1><<<dim3(H_/128, MS_/128), blk>>>(ckv, whi+OFF_UK, wlo+OFF_UK, b_UK,
                                                  nullptr, khi, klo, MS_, H_, LAT_, 640);       // 12
    gemm_bf16s<2><<<dim3(H_/128, MS_/128), blk>>>(ckv, whi+OFF_UV, wlo+OFF_UV, b_UV,
                                                  nullptr, vthi, vtlo, MS_, H_, LAT_, 640);     // 13
    gemm_bf16s<1><<<dim3(H_/128, MS_/128), blk>>>(cq, whi+OFF_UQ, wlo+OFF_UQ, b_UQ,
                                                  nullptr, qhi, qlo, MS_, H_, LAT_, 640);       // 14
    split_transpose<<<dim3(H_/32, H_/32), tblk>>>(W_O, whi+OFF_O, wlo+OFF_O, H_, H_);           // 15

    // attention
    mla_attn_mma<<<dim3(S_/64, NH_, B_), 256, AT_SMEM>>>(
        qhi, qlo, qrh, qrl, khi, klo, krh, krl, vthi, vtlo, mask, ctx);                         // 16

    // output projection
    gemm_bf16s<0><<<dim3(H_/128, MS_/128), blk>>>(ctx, whi+OFF_O, wlo+OFF_O, b_O,
                                                  out, nullptr, nullptr, MS_, H_, H_, H_);      // 17
}

// round 17
// speedup vs baseline: 1.0227x; 1.0227x over previous
#include <cuda_runtime.h>
#include <cuda_bf16.h>
#include <math.h>

#define B_   2
#define S_   2048
#define H_   2048
#define NH_  16
#define D_   128
#define LAT_ 512
#define MS_  (B_*S_)   // 4096 rows total

// ---------------- scratch (device globals; no allocation allowed) ----------
__device__ float g_bKV[640];
__device__ float g_bQ [640];

// pre-split bf16 activations (hi + lo residual everywhere)
__device__ __nv_bfloat16 g_hsh [MS_*H_],  g_hsl [MS_*H_];    // hidden_states
__device__ __nv_bfloat16 g_ckvh[MS_*640], g_ckvl[MS_*640];   // [c_kv|k_r] stride 640
__device__ __nv_bfloat16 g_cqh [MS_*640], g_cql [MS_*640];   // [c_q |q_r]
__device__ __nv_bfloat16 g_ctxh[MS_*H_],  g_ctxl[MS_*H_];    // attention output
__device__ __nv_bfloat16 g_khi [MS_*H_],  g_klo [MS_*H_];    // K_c  [row][H]
__device__ __nv_bfloat16 g_qhi [MS_*H_],  g_qlo [MS_*H_];    // Q_c  [row][H]
__device__ __nv_bfloat16 g_vthi[MS_*H_],  g_vtlo[MS_*H_];    // V^T  [H][MS]
__device__ __nv_bfloat16 g_krh [MS_*D_],  g_krl [MS_*D_];    // rope(K_r)
__device__ __nv_bfloat16 g_qrh [MS_*D_],  g_qrl [MS_*D_];    // rope(Q_r)

// pre-split / transposed bf16 weights ([N][K] layout), hi + lo residual
#define OFF_DKV 0                    // 640 x 2048 (DKV rows 0-511, KR rows 512-639)
#define OFF_KR  1048576
#define OFF_DQ  1310720              // 640 x 2048
#define OFF_QR  2359296
#define OFF_UK  2621440              // 2048 x 512
#define OFF_UV  3670016
#define OFF_UQ  4718592
#define OFF_O   5767168              // 2048 x 2048
#define WTOT    9961472
__device__ __nv_bfloat16 g_whi[WTOT];
__device__ __nv_bfloat16 g_wlo[WTOT];

// ---------------- split helper: float4 -> packed bf16 hi/lo ----------------
__device__ __forceinline__ void split4(float4 v, uint2& h, uint2& l)
{
    __nv_bfloat162 h0 = __floats2bfloat162_rn(v.x, v.y);
    __nv_bfloat162 h1 = __floats2bfloat162_rn(v.z, v.w);
    float2 f0 = __bfloat1622float2(h0);
    float2 f1 = __bfloat1622float2(h1);
    __nv_bfloat162 l0 = __floats2bfloat162_rn(v.x - f0.x, v.y - f0.y);
    __nv_bfloat162 l1 = __floats2bfloat162_rn(v.z - f1.x, v.w - f1.y);
    h.x = *(unsigned*)&h0; h.y = *(unsigned*)&h1;
    l.x = *(unsigned*)&l0; l.y = *(unsigned*)&l1;
}

// ---------------- weight split + transpose: W[K][N] -> hi/lo [N][K] --------
__global__ void split_transpose(const float* __restrict__ W,
                                __nv_bfloat16* __restrict__ hi,
                                __nv_bfloat16* __restrict__ lo,
                                int K, int N)
{
    __shared__ float tile[32][33];
    const int k0 = blockIdx.y * 32, n0 = blockIdx.x * 32;
    const int tx = threadIdx.x, ty = threadIdx.y;   // 32 x 8
#pragma unroll
    for (int i = ty; i < 32; i += 8)
        tile[i][tx] = W[(k0 + i) * N + n0 + tx];
    __syncthreads();
#pragma unroll
    for (int i = ty; i < 32; i += 8) {
        float v = tile[tx][i];
        __nv_bfloat16 h = __float2bfloat16(v);
        float r = v - __bfloat162float(h);
        hi[(n0 + i) * (long)K + k0 + tx] = h;
        lo[(n0 + i) * (long)K + k0 + tx] = __float2bfloat16(r);
    }
}

// ---------------- activation split: fp32 -> bf16 hi/lo (+bias fuse) --------
__global__ void split_act(const float* __restrict__ x,
                          __nv_bfloat16* __restrict__ xh,
                          __nv_bfloat16* __restrict__ xl,
                          float* bkv, float* bq,
                          const float* bDKV, const float* bKR,
                          const float* bDQ,  const float* bQR)
{
    long i = (long)blockIdx.x * 1024 + threadIdx.x * 4;
    float4 v = *(const float4*)&x[i];
    uint2 h, l;
    split4(v, h, l);
    *(uint2*)&xh[i] = h;
    *(uint2*)&xl[i] = l;
    if (blockIdx.x == 0) {
        for (int j = threadIdx.x; j < 512; j += 256) {
            bkv[j] = bDKV[j]; bq[j] = bDQ[j];
        }
        for (int j = threadIdx.x; j < 128; j += 256) {
            bkv[512 + j] = bKR[j]; bq[512 + j] = bQR[j];
        }
    }
}

__device__ __forceinline__ void mma16816(float* c, const unsigned* a,
                                         unsigned b0, unsigned b1)
{
    asm volatile(
        "mma.sync.aligned.m16n8k16.row.col.f32.bf16.bf16.f32 "
        "{%0,%1,%2,%3}, {%4,%5,%6,%7}, {%8,%9}, {%0,%1,%2,%3};\n"
        : "+f"(c[0]), "+f"(c[1]), "+f"(c[2]), "+f"(c[3])
        : "r"(a[0]), "r"(a[1]), "r"(a[2]), "r"(a[3]), "r"(b0), "r"(b1));
}

// ---------------- bf16-split tensor-core GEMM (cp.async pipeline) ----------
// C[M][N] = (Ahi+Alo)[M][K] @ W(hi/lo [N][K]) + bias, 3-pass hi/lo.
// BM=128, BN=128, BK=32, 256 threads, 2-stage cp.async double buffer.
// MODE 0: fp32 C. MODE 1: bf16 hi/lo row-major. MODE 2: bf16 hi/lo transposed.
#define GST_B 40960     // bytes per stage (4 arrays x 128 x 40 bf16)
#define GARRE 5120      // bf16 elems per array
template<int MODE>
__global__ __launch_bounds__(256, 2) void gemm_bf16s(
    const __nv_bfloat16* __restrict__ Ahi, const __nv_bfloat16* __restrict__ Alo,
    const __nv_bfloat16* __restrict__ Bhi, const __nv_bfloat16* __restrict__ Blo,
    const float* __restrict__ bias, float* __restrict__ C,
    __nv_bfloat16* __restrict__ Chi, __nv_bfloat16* __restrict__ Clo,
    int M, int N, int K, int lda)
{
    extern __shared__ __align__(16) __nv_bfloat16 smg[];

    const int tid  = threadIdx.x;
    const int wid  = tid >> 5, lane = tid & 31;
    const int row0 = blockIdx.y * 128, col0 = blockIdx.x * 128;
    const int wm   = (wid >> 1) * 32, wn = (wid & 1) * 64;

    float acc[2][8][4];
#pragma unroll
    for (int t = 0; t < 2; t++)
#pragma unroll
        for (int n = 0; n < 8; n++)
#pragma unroll
            for (int j = 0; j < 4; j++) acc[t][n][j] = 0.f;

    const unsigned sbase = (unsigned)__cvta_generic_to_shared(smg);

    // chunk mapping: thread handles chunks tid and tid+256 per array.
    // chunk c: row = c>>2, 16B-piece = c&3. smem row stride 40 bf16 (80 B).
#define ISSUE_STAGE(k0, stg)                                                  \
    {                                                                         \
        unsigned sb = sbase + (stg) * GST_B;                                  \
        _Pragma("unroll")                                                     \
        for (int hf = 0; hf < 2; hf++) {                                      \
            int c = tid + hf * 256;                                           \
            int r = c >> 2, ce = (c & 3) * 8;                                 \
            unsigned so = r * 80 + (c & 3) * 16;                              \
            const __nv_bfloat16* gah = Ahi + (long)(row0 + r) * lda + (k0) + ce; \
            const __nv_bfloat16* gal = Alo + (long)(row0 + r) * lda + (k0) + ce; \
            const __nv_bfloat16* gbh = Bhi + (long)(col0 + r) * K + (k0) + ce;   \
            const __nv_bfloat16* gbl = Blo + (long)(col0 + r) * K + (k0) + ce;   \
            asm volatile("cp.async.cg.shared.global [%0], [%1], 16;\n"        \
                         :: "r"(sb + so), "l"(gah));                          \
            asm volatile("cp.async.cg.shared.global [%0], [%1], 16;\n"        \
                         :: "r"(sb + 10240 + so), "l"(gal));                  \
            asm volatile("cp.async.cg.shared.global [%0], [%1], 16;\n"        \
                         :: "r"(sb + 20480 + so), "l"(gbh));                  \
            asm volatile("cp.async.cg.shared.global [%0], [%1], 16;\n"        \
                         :: "r"(sb + 30720 + so), "l"(gbl));                  \
        }                                                                     \
        asm volatile("cp.async.commit_group;\n");                             \
    }

    const int nk = K >> 5;
    ISSUE_STAGE(0, 0);
    if (nk > 1) ISSUE_STAGE(32, 1);

#pragma unroll 1
    for (int kk = 0; kk < nk; kk++) {
        const int cur = kk & 1;
        if (kk + 1 < nk) { asm volatile("cp.async.wait_group 1;\n"); }
        else             { asm volatile("cp.async.wait_group 0;\n"); }
        __syncthreads();

        const __nv_bfloat16* sA  = smg + cur * (GST_B / 2);
        const __nv_bfloat16* sAl = sA + GARRE;
        const __nv_bfloat16* sB  = sA + 2 * GARRE;
        const __nv_bfloat16* sBl = sA + 3 * GARRE;

#pragma unroll
        for (int s = 0; s < 2; s++) {
            const int c = s * 16 + (lane & 3) * 2;
            unsigned afh[2][4], afl[2][4];
#pragma unroll
            for (int t = 0; t < 2; t++) {
                int r = wm + t * 16 + (lane >> 2);
                afh[t][0] = *(unsigned*)&sA [r * 40 + c];
                afh[t][1] = *(unsigned*)&sA [(r + 8) * 40 + c];
                afh[t][2] = *(unsigned*)&sA [r * 40 + c + 8];
                afh[t][3] = *(unsigned*)&sA [(r + 8) * 40 + c + 8];
                afl[t][0] = *(unsigned*)&sAl[r * 40 + c];
                afl[t][1] = *(unsigned*)&sAl[(r + 8) * 40 + c];
                afl[t][2] = *(unsigned*)&sAl[r * 40 + c + 8];
                afl[t][3] = *(unsigned*)&sAl[(r + 8) * 40 + c + 8];
            }
#pragma unroll
            for (int nt = 0; nt < 8; nt++) {
                int n = wn + nt * 8 + (lane >> 2);
                unsigned bh0 = *(unsigned*)&sB [n * 40 + c];
                unsigned bh1 = *(unsigned*)&sB [n * 40 + c + 8];
                unsigned bl0 = *(unsigned*)&sBl[n * 40 + c];
                unsigned bl1 = *(unsigned*)&sBl[n * 40 + c + 8];
#pragma unroll
                for (int t = 0; t < 2; t++) {
                    mma16816(acc[t][nt], afh[t], bh0, bh1);
                    mma16816(acc[t][nt], afh[t], bl0, bl1);
                    mma16816(acc[t][nt], afl[t], bh0, bh1);
                }
            }
        }

        __syncthreads();
        if (kk + 2 < nk) ISSUE_STAGE((kk + 2) * 32, cur);
    }

#pragma unroll
    for (int t = 0; t < 2; t++) {
        int gr = row0 + wm + t * 16 + (lane >> 2);
#pragma unroll
        for (int nt = 0; nt < 8; nt++) {
            int gc = col0 + wn + nt * 8 + (lane & 3) * 2;
            float2 bv = *(const float2*)&bias[gc];
            float v0 = acc[t][nt][0] + bv.x, v1 = acc[t][nt][1] + bv.y;
            float v2 = acc[t][nt][2] + bv.x, v3 = acc[t][nt][3] + bv.y;
            if (MODE == 0) {
                *(float2*)&C[(long)gr * N + gc]       = make_float2(v0, v1);
                *(float2*)&C[(long)(gr + 8) * N + gc] = make_float2(v2, v3);
            } else if (MODE == 1) {
                __nv_bfloat162 h01 = __floats2bfloat162_rn(v0, v1);
                float2 f01 = __bfloat1622float2(h01);
                __nv_bfloat162 q01 = __floats2bfloat162_rn(v0 - f01.x, v1 - f01.y);
                __nv_bfloat162 h23 = __floats2bfloat162_rn(v2, v3);
                float2 f23 = __bfloat1622float2(h23);
                __nv_bfloat162 q23 = __floats2bfloat162_rn(v2 - f23.x, v3 - f23.y);
                *(__nv_bfloat162*)&Chi[(long)gr * N + gc]       = h01;
                *(__nv_bfloat162*)&Clo[(long)gr * N + gc]       = q01;
                *(__nv_bfloat162*)&Chi[(long)(gr + 8) * N + gc] = h23;
                *(__nv_bfloat162*)&Clo[(long)(gr + 8) * N + gc] = q23;
            } else {
                float vs[4] = {v0, v1, v2, v3};
#pragma unroll
                for (int q = 0; q < 4; q++) {
                    long idx = (long)(gc + (q & 1)) * MS_ + gr + (q >> 1) * 8;
                    __nv_bfloat16 hh = __float2bfloat16(vs[q]);
                    Chi[idx] = hh;
                    Clo[idx] = __float2bfloat16(vs[q] - __bfloat162float(hh));
                }
            }
        }
    }
#undef ISSUE_STAGE
}

// ---------------- rope: bf16 hi/lo in (strided) -> bf16 hi/lo out ----------
__global__ void rope_kernel(const __nv_bfloat16* __restrict__ xh,
                            const __nv_bfloat16* __restrict__ xl, int ldx,
                            __nv_bfloat16* __restrict__ oh,
                            __nv_bfloat16* __restrict__ ol)
{
    int row = blockIdx.x;
    int d   = threadIdx.x;
    __shared__ float buf[128];
    buf[d] = __bfloat162float(xh[(long)row * ldx + d]) +
             __bfloat162float(xl[(long)row * ldx + d]);
    __syncthreads();
    int i = d & 63;
    float inv = (float)exp(-(double)(2 * i) / 128.0 * 9.210340371976184);
    float ang = (float)(row & (S_ - 1)) * inv;
    float s, c;
    sincosf(ang, &s, &c);
    float y = (d < 64) ? (buf[d] * c - buf[d + 64] * s)
                       : (buf[d - 64] * s + buf[d] * c);
    __nv_bfloat16 h = __float2bfloat16(y);
    oh[row * D_ + d] = h;
    ol[row * D_ + d] = __float2bfloat16(y - __bfloat162float(h));
}

// ---------------- coalesced Q/K tile loader --------------------------------
__device__ __forceinline__ void load_qk_tile(
    __nv_bfloat16* DH, __nv_bfloat16* DL,
    const __nv_bfloat16* __restrict__ chi_, const __nv_bfloat16* __restrict__ clo_,
    const __nv_bfloat16* __restrict__ rh_,  const __nv_bfloat16* __restrict__ rl_,
    long rowbase, int hD, int t)
{
#pragma unroll
    for (int it = 0; it < 16; it++) {
        int seg = (t >> 4) + it * 16;       // 0..255
        int row = seg >> 2, src = seg & 3;  // 0=c-hi 1=r-hi 2=c-lo 3=r-lo
        int c16 = t & 15;
        long rg = rowbase + row;
        const uint4* s;
        if (src == 0)      s = (const uint4*)(chi_ + rg * H_ + hD) + c16;
        else if (src == 1) s = (const uint4*)(rh_  + rg * D_)      + c16;
        else if (src == 2) s = (const uint4*)(clo_ + rg * H_ + hD) + c16;
        else               s = (const uint4*)(rl_  + rg * D_)      + c16;
        __nv_bfloat16* db = (src & 2) ? DL : DH;
        *((uint4*)(db + row * 264 + (src & 1) * 128) + c16) = *s;
    }
}

// ---------------- tensor-core flash attention (bf16 3-pass split) ----------
#define AT_SMEM 191744
__global__ __launch_bounds__(256, 1) void mla_attn_mma(
    const __nv_bfloat16* __restrict__ qhi, const __nv_bfloat16* __restrict__ qlo,
    const __nv_bfloat16* __restrict__ qrh, const __nv_bfloat16* __restrict__ qrl,
    const __nv_bfloat16* __restrict__ khi, const __nv_bfloat16* __restrict__ klo,
    const __nv_bfloat16* __restrict__ krh, const __nv_bfloat16* __restrict__ krl,
    const __nv_bfloat16* __restrict__ vth, const __nv_bfloat16* __restrict__ vtl,
    const int* __restrict__ mask,
    __nv_bfloat16* __restrict__ ctxh, __nv_bfloat16* __restrict__ ctxl)
{
    extern __shared__ __align__(16) char smx[];
    __nv_bfloat16* QH = (__nv_bfloat16*)smx;
    __nv_bfloat16* QL = QH + 64 * 264;
    __nv_bfloat16* KH = QL + 64 * 264;
    __nv_bfloat16* KL = KH + 64 * 264;
    __nv_bfloat16* VH = KL + 64 * 264;
    __nv_bfloat16* VL = VH + 128 * 72;
    __nv_bfloat16* PH = VL + 128 * 72;
    __nv_bfloat16* PL = PH + 64 * 72;
    float*         MB = (float*)(PL + 64 * 72);
    float*         SMX = MB + 64;
    float*         SMS = SMX + 128;

    const int t    = threadIdx.x;
    const int lane = t & 31, w = t >> 5;
    const int wg   = w >> 2, wr = w & 3;
    const int b = blockIdx.z, h = blockIdx.y;
    const int q0 = blockIdx.x * 64;
    const int r0 = wr * 16;
    const int ru = lane >> 2, rv = lane & 3;

    load_qk_tile(QH, QL, qhi, qlo, qrh, qrl, (long)(b * S_ + q0), h * D_, t);

    float oacc[16][4];
#pragma unroll
    for (int i = 0; i < 16; i++)
#pragma unroll
        for (int j = 0; j < 4; j++) oacc[i][j] = 0.f;
    float m0 = -1e30f, m1 = -1e30f, l0 = 0.f, l1 = 0.f;
    const float scale = 0.08838834764831845f;   // 1/sqrt(128)

    const unsigned* QHw = (const unsigned*)QH;
    const unsigned* QLw = (const unsigned*)QL;
    const unsigned* KHw = (const unsigned*)KH;
    const unsigned* KLw = (const unsigned*)KL;
    const unsigned* VHw = (const unsigned*)VH;
    const unsigned* VLw = (const unsigned*)VL;
    unsigned* PHw = (unsigned*)PH;
    unsigned* PLw = (unsigned*)PL;

    for (int s0 = 0; s0 < S_; s0 += 64) {
        __syncthreads();
        load_qk_tile(KH, KL, khi, klo, krh, krl, (long)(b * S_ + s0), h * D_, t);
#pragma unroll
        for (int it = 0; it < 8; it++) {
            int slot = t + it * 256;
            int seg = slot >> 3, c4 = slot & 7;
            int vd = seg & 127, hl = seg >> 7;
            const __nv_bfloat16* sb = hl ? vtl : vth;
            const uint4* s = (const uint4*)(sb + (long)(h * D_ + vd) * MS_ + b * S_ + s0) + c4;
            __nv_bfloat16* db = hl ? VL : VH;
            *((uint4*)(db + vd * 72) + c4) = *s;
        }
        if (t < 64) MB[t] = mask[b * S_ + s0 + t] ? 0.f : -1e30f;
        __syncthreads();

        // ---- QK^T (3-pass), this group's 4 column tiles ----
        float sacc[4][4];
#pragma unroll
        for (int i = 0; i < 4; i++)
#pragma unroll
            for (int j = 0; j < 4; j++) sacc[i][j] = 0.f;
#pragma unroll 1
        for (int ch = 0; ch < 16; ch++) {
            unsigned ah[4], al[4];
            int ab = (r0 + ru) * 132 + ch * 8 + rv;
            ah[0] = QHw[ab];     ah[1] = QHw[ab + 8*132];
            ah[2] = QHw[ab + 4]; ah[3] = QHw[ab + 8*132 + 4];
            al[0] = QLw[ab];     al[1] = QLw[ab + 8*132];
            al[2] = QLw[ab + 4]; al[3] = QLw[ab + 8*132 + 4];
#pragma unroll
            for (int nt = 0; nt < 4; nt++) {
                int gnt = wg * 4 + nt;
                int bb = (gnt * 8 + ru) * 132 + ch * 8 + rv;
                unsigned bh0 = KHw[bb], bh1 = KHw[bb + 4];
                unsigned bl0 = KLw[bb], bl1 = KLw[bb + 4];
                mma16816(sacc[nt], ah, bh0, bh1);
                mma16816(sacc[nt], ah, bl0, bl1);
                mma16816(sacc[nt], al, bh0, bh1);
            }
        }

        // ---- partial row max ----
        float mx0 = -1e30f, mx1 = -1e30f;
#pragma unroll
        for (int nt = 0; nt < 4; nt++) {
            int col = (wg * 4 + nt) * 8 + rv * 2;
            float mb0 = MB[col], mb1 = MB[col + 1];
            sacc[nt][0] = sacc[nt][0] * scale + mb0;
            sacc[nt][1] = sacc[nt][1] * scale + mb1;
            sacc[nt][2] = sacc[nt][2] * scale + mb0;
            sacc[nt][3] = sacc[nt][3] * scale + mb1;
            mx0 = fmaxf(mx0, fmaxf(sacc[nt][0], sacc[nt][1]));
            mx1 = fmaxf(mx1, fmaxf(sacc[nt][2], sacc[nt][3]));
        }
        mx0 = fmaxf(mx0, __shfl_xor_sync(0xffffffffu, mx0, 1));
        mx0 = fmaxf(mx0, __shfl_xor_sync(0xffffffffu, mx0, 2));
        mx1 = fmaxf(mx1, __shfl_xor_sync(0xffffffffu, mx1, 1));
        mx1 = fmaxf(mx1, __shfl_xor_sync(0xffffffffu, mx1, 2));
        if (rv == 0) {
            SMX[wg * 64 + r0 + ru]     = mx0;
            SMX[wg * 64 + r0 + ru + 8] = mx1;
        }
        __syncthreads();
        float gm0 = fmaxf(SMX[r0 + ru],     SMX[64 + r0 + ru]);
        float gm1 = fmaxf(SMX[r0 + ru + 8], SMX[64 + r0 + ru + 8]);
        float mn0 = fmaxf(m0, gm0), mn1 = fmaxf(m1, gm1);
        float cr0 = __expf(m0 - mn0), cr1 = __expf(m1 - mn1);
        m0 = mn0; m1 = mn1;
#pragma unroll
        for (int nt = 0; nt < 16; nt++) {
            oacc[nt][0] *= cr0; oacc[nt][1] *= cr0;
            oacc[nt][2] *= cr1; oacc[nt][3] *= cr1;
        }
        float rs0 = 0.f, rs1 = 0.f;
#pragma unroll
        for (int nt = 0; nt < 4; nt++) {
            float p0 = __expf(sacc[nt][0] - mn0), p1 = __expf(sacc[nt][1] - mn0);
            float p2 = __expf(sacc[nt][2] - mn1), p3 = __expf(sacc[nt][3] - mn1);
            rs0 += p0 + p1; rs1 += p2 + p3;
            __nv_bfloat162 h01 = __floats2bfloat162_rn(p0, p1);
            float2 f01 = __bfloat1622float2(h01);
            __nv_bfloat162 q01 = __floats2bfloat162_rn(p0 - f01.x, p1 - f01.y);
            __nv_bfloat162 h23 = __floats2bfloat162_rn(p2, p3);
            float2 f23 = __bfloat1622float2(h23);
            __nv_bfloat162 q23 = __floats2bfloat162_rn(p2 - f23.x, p3 - f23.y);
            int gnt = wg * 4 + nt;
            int w0 = (r0 + ru) * 36 + gnt * 4 + rv;
            int w1 = (r0 + ru + 8) * 36 + gnt * 4 + rv;
            PHw[w0] = *(unsigned*)&h01; PLw[w0] = *(unsigned*)&q01;
            PHw[w1] = *(unsigned*)&h23; PLw[w1] = *(unsigned*)&q23;
        }
        rs0 += __shfl_xor_sync(0xffffffffu, rs0, 1);
        rs0 += __shfl_xor_sync(0xffffffffu, rs0, 2);
        rs1 += __shfl_xor_sync(0xffffffffu, rs1, 1);
        rs1 += __shfl_xor_sync(0xffffffffu, rs1, 2);
        if (rv == 0) {
            SMS[wg * 64 + r0 + ru]     = rs0;
            SMS[wg * 64 + r0 + ru + 8] = rs1;
        }
        __syncthreads();
        l0 = l0 * cr0 + SMS[r0 + ru]     + SMS[64 + r0 + ru];
        l1 = l1 * cr1 + SMS[r0 + ru + 8] + SMS[64 + r0 + ru + 8];

        // ---- P @ V (3-pass), this group's 32 keys ----
#pragma unroll 1
        for (int chl = 0; chl < 2; chl++) {
            int ch = wg * 2 + chl;
            unsigned ph[4], pl[4];
            int ab = (r0 + ru) * 36 + ch * 8 + rv;
            ph[0] = PHw[ab];     ph[1] = PHw[ab + 8*36];
            ph[2] = PHw[ab + 4]; ph[3] = PHw[ab + 8*36 + 4];
            pl[0] = PLw[ab];     pl[1] = PLw[ab + 8*36];
            pl[2] = PLw[ab + 4]; pl[3] = PLw[ab + 8*36 + 4];
#pragma unroll
            for (int nt = 0; nt < 16; nt++) {
                int bb = (nt * 8 + ru) * 36 + ch * 8 + rv;
                unsigned vh0 = VHw[bb], vh1 = VHw[bb + 4];
                unsigned vl0 = VLw[bb], vl1 = VLw[bb + 4];
                mma16816(oacc[nt], ph, vh0, vh1);
                mma16816(oacc[nt], ph, vl0, vl1);
                mma16816(oacc[nt], pl, vh0, vh1);
            }
        }
    }

    // ---- combine the two groups' partial PV sums ----
    __syncthreads();
    float* OC = (float*)KH;
    if (wg == 1) {
#pragma unroll
        for (int nt = 0; nt < 16; nt++) {
            int d0 = nt * 8 + rv * 2;
            *(float2*)&OC[(r0 + ru) * 132 + d0] =
                make_float2(oacc[nt][0], oacc[nt][1]);
            *(float2*)&OC[(r0 + ru + 8) * 132 + d0] =
                make_float2(oacc[nt][2], oacc[nt][3]);
        }
    }
    __syncthreads();
    if (wg == 0) {
        float inv0 = 1.f / l0, inv1 = 1.f / l1;
        long row0 = (long)(b * S_ + q0 + r0 + ru);
#pragma unroll
        for (int nt = 0; nt < 16; nt++) {
            int d0 = nt * 8 + rv * 2;
            float2 pB0 = *(float2*)&OC[(r0 + ru) * 132 + d0];
            float2 pB1 = *(float2*)&OC[(r0 + ru + 8) * 132 + d0];
            float a0 = (oacc[nt][0] + pB0.x) * inv0;
            float a1 = (oacc[nt][1] + pB0.y) * inv0;
            float a2 = (oacc[nt][2] + pB1.x) * inv1;
            float a3 = (oacc[nt][3] + pB1.y) * inv1;
            __nv_bfloat162 h01 = __floats2bfloat162_rn(a0, a1);
            float2 f01 = __bfloat1622float2(h01);
            __nv_bfloat162 q01 = __floats2bfloat162_rn(a0 - f01.x, a1 - f01.y);
            __nv_bfloat162 h23 = __floats2bfloat162_rn(a2, a3);
            float2 f23 = __bfloat1622float2(h23);
            __nv_bfloat162 q23 = __floats2bfloat162_rn(a2 - f23.x, a3 - f23.y);
            *(__nv_bfloat162*)&ctxh[row0 * H_ + h * D_ + d0]       = h01;
            *(__nv_bfloat162*)&ctxl[row0 * H_ + h * D_ + d0]       = q01;
            *(__nv_bfloat162*)&ctxh[(row0 + 8) * H_ + h * D_ + d0] = h23;
            *(__nv_bfloat162*)&ctxl[(row0 + 8) * H_ + h * D_ + d0] = q23;
        }
    }
}

// ---------------- launch ----------------------------------------------------
extern "C" void kernel_launch(void* const* d_in, const int* in_sizes, int n_in,
                              void* d_out, int out_size)
{
    const float* hs    = (const float*)d_in[0];
    const int*   mask  = (const int*)  d_in[1];
    const float* W_DKV = (const float*)d_in[2];  const float* b_DKV = (const float*)d_in[3];
    const float* W_DQ  = (const float*)d_in[4];  const float* b_DQ  = (const float*)d_in[5];
    const float* W_UK  = (const float*)d_in[6];  const float* b_UK  = (const float*)d_in[7];
    const float* W_UV  = (const float*)d_in[8];  const float* b_UV  = (const float*)d_in[9];
    const float* W_UQ  = (const float*)d_in[10]; const float* b_UQ  = (const float*)d_in[11];
    const float* W_KR  = (const float*)d_in[12]; const float* b_KR  = (const float*)d_in[13];
    const float* W_QR  = (const float*)d_in[14]; const float* b_QR  = (const float*)d_in[15];
    const float* W_O   = (const float*)d_in[16]; const float* b_O   = (const float*)d_in[17];
    float* out = (float*)d_out;

    float *bkv, *bq;
    __nv_bfloat16 *whi, *wlo, *hsh, *hsl, *ckvh, *ckvl, *cqh, *cql, *ctxh, *ctxl;
    __nv_bfloat16 *khi, *klo, *qhi, *qlo, *vthi, *vtlo, *krh, *krl, *qrh, *qrl;
    cudaGetSymbolAddress((void**)&bkv,  g_bKV);
    cudaGetSymbolAddress((void**)&bq,   g_bQ);
    cudaGetSymbolAddress((void**)&whi,  g_whi);
    cudaGetSymbolAddress((void**)&wlo,  g_wlo);
    cudaGetSymbolAddress((void**)&hsh,  g_hsh);
    cudaGetSymbolAddress((void**)&hsl,  g_hsl);
    cudaGetSymbolAddress((void**)&ckvh, g_ckvh);
    cudaGetSymbolAddress((void**)&ckvl, g_ckvl);
    cudaGetSymbolAddress((void**)&cqh,  g_cqh);
    cudaGetSymbolAddress((void**)&cql,  g_cql);
    cudaGetSymbolAddress((void**)&ctxh, g_ctxh);
    cudaGetSymbolAddress((void**)&ctxl, g_ctxl);
    cudaGetSymbolAddress((void**)&khi,  g_khi);
    cudaGetSymbolAddress((void**)&klo,  g_klo);
    cudaGetSymbolAddress((void**)&qhi,  g_qhi);
    cudaGetSymbolAddress((void**)&qlo,  g_qlo);
    cudaGetSymbolAddress((void**)&vthi, g_vthi);
    cudaGetSymbolAddress((void**)&vtlo, g_vtlo);
    cudaGetSymbolAddress((void**)&krh,  g_krh);
    cudaGetSymbolAddress((void**)&krl,  g_krl);
    cudaGetSymbolAddress((void**)&qrh,  g_qrh);
    cudaGetSymbolAddress((void**)&qrl,  g_qrl);

    cudaFuncSetAttribute(mla_attn_mma,
                         cudaFuncAttributeMaxDynamicSharedMemorySize, AT_SMEM);
    cudaFuncSetAttribute(gemm_bf16s<0>,
                         cudaFuncAttributeMaxDynamicSharedMemorySize, 2 * GST_B);
    cudaFuncSetAttribute(gemm_bf16s<1>,
                         cudaFuncAttributeMaxDynamicSharedMemorySize, 2 * GST_B);
    cudaFuncSetAttribute(gemm_bf16s<2>,
                         cudaFuncAttributeMaxDynamicSharedMemorySize, 2 * GST_B);
    const int GS = 2 * GST_B;   // 81920 B

    const dim3 blk(256);
    const dim3 tblk(32, 8);

    // launches 1-5, so #6 (ncu -s 5 -c 1) is the big fused DKV GEMM
    split_transpose<<<dim3(LAT_/32, H_/32), tblk>>>(W_DKV, whi+OFF_DKV, wlo+OFF_DKV, H_, LAT_); // 1
    split_transpose<<<dim3(D_/32,   H_/32), tblk>>>(W_KR,  whi+OFF_KR,  wlo+OFF_KR,  H_, D_);   // 2
    split_act<<<MS_*H_/1024, 256>>>(hs, hsh, hsl, bkv, bq, b_DKV, b_KR, b_DQ, b_QR);            // 3
    split_transpose<<<dim3(LAT_/32, H_/32), tblk>>>(W_DQ,  whi+OFF_DQ,  wlo+OFF_DQ,  H_, LAT_); // 4
    split_transpose<<<dim3(D_/32,   H_/32), tblk>>>(W_QR,  whi+OFF_QR,  wlo+OFF_QR,  H_, D_);   // 5

    // fused down-projections: rows = [c_kv | k_r] (stride 640), bf16 hi/lo out
    gemm_bf16s<1><<<dim3(5, MS_/128), blk, GS>>>(hsh, hsl, whi+OFF_DKV, wlo+OFF_DKV, bkv,
                                                 nullptr, ckvh, ckvl, MS_, 640, H_, H_);        // 6 (profiled)
    split_transpose<<<dim3(H_/32, LAT_/32), tblk>>>(W_UK, whi+OFF_UK, wlo+OFF_UK, LAT_, H_);    // 7
    gemm_bf16s<1><<<dim3(5, MS_/128), blk, GS>>>(hsh, hsl, whi+OFF_DQ, wlo+OFF_DQ, bq,
                                                 nullptr, cqh, cql, MS_, 640, H_, H_);          // 8
    rope_kernel<<<MS_, 128>>>(ckvh + 512, ckvl + 512, 640, krh, krl);                           // 9
    rope_kernel<<<MS_, 128>>>(cqh + 512, cql + 512, 640, qrh, qrl);                             // 10
    split_transpose<<<dim3(H_/32, LAT_/32), tblk>>>(W_UV, whi+OFF_UV, wlo+OFF_UV, LAT_, H_);    // 11
    split_transpose<<<dim3(H_/32, LAT_/32), tblk>>>(W_UQ, whi+OFF_UQ, wlo+OFF_UQ, LAT_, H_);    // 12

    // up-projections (A = pre-split c_kv / c_q, row stride 640)
    gemm_bf16s<1><<<dim3(H_/128, MS_/128), blk, GS>>>(ckvh, ckvl, whi+OFF_UK, wlo+OFF_UK, b_UK,
                                                      nullptr, khi, klo, MS_, H_, LAT_, 640);   // 13
    gemm_bf16s<2><<<dim3(H_/128, MS_/128), blk, GS>>>(ckvh, ckvl, whi+OFF_UV, wlo+OFF_UV, b_UV,
                                                      nullptr, vthi, vtlo, MS_, H_, LAT_, 640); // 14
    gemm_bf16s<1><<<dim3(H_/128, MS_/128), blk, GS>>>(cqh, cql, whi+OFF_UQ, wlo+OFF_UQ, b_UQ,
                                                      nullptr, qhi, qlo, MS_, H_, LAT_, 640);   // 15
    split_transpose<<<dim3(H_/32, H_/32), tblk>>>(W_O, whi+OFF_O, wlo+OFF_O, H_, H_);           // 16

    // attention (emits pre-split ctx)
    mla_attn_mma<<<dim3(S_/64, NH_, B_), 256, AT_SMEM>>>(
        qhi, qlo, qrh, qrl, khi, klo, krh, krl, vthi, vtlo, mask, ctxh, ctxl);                  // 17

    // output projection (fp32 out)
    gemm_bf16s<0><<<dim3(H_/128, MS_/128), blk, GS>>>(ctxh, ctxl, whi+OFF_O, wlo+OFF_O, b_O,
                                                      out, nullptr, nullptr, MS_, H_, H_, H_);  // 18
}